// round 1
// baseline (speedup 1.0000x reference)
#include <cuda_runtime.h>
#include <math.h>
#include <float.h>

// Problem constants
#define NS 25      // support count (WAY*SHOT)
#define NQ 75      // query count (WAY*QUERY_SHOT)
#define DD 640     // feature dim
#define MM 25      // M (inner dim)

// Scratch (device globals; no runtime allocation allowed)
__device__ float g_P[NQ * NS * DD];   // P[q][s][d] = sum_m S[s,d,m]*W[s,q,m]  (unnormalized)
__device__ float g_l2[NQ * NS];       // raw sum_d (p-r)^2, indexed [q][s]

// ---------------------------------------------------------------------------
// Kernel 1: per-s GEMM. P[q][s][d] = sum_m W[s,q,m] * S[s,d,m]
// grid = (10 d-groups of 64, 25 s), block = 256 threads, thread tile 5q x 4d
// Also zeroes g_l2 (block (0,0)) so K2 atomics start clean every replay.
// ---------------------------------------------------------------------------
__global__ void k1_proj_support(const float* __restrict__ fm,
                                const float* __restrict__ w2) {
    const int s  = blockIdx.y;
    const int d0 = blockIdx.x * 64;

    __shared__ __align__(16) float Wsm[MM][84];  // [m][q], q padded to 80 (+bank pad)
    __shared__ __align__(16) float Ssm[MM][68];  // [m][d], 64 d (+bank pad)

    const int tid = threadIdx.x;

    // Stage W[s,:,:] -> Wsm[m][q]  (global reads fully coalesced)
    for (int idx = tid; idx < NQ * MM; idx += 256) {
        int q = idx / MM, m = idx - q * MM;
        Wsm[m][q] = w2[s * (NQ * MM) + idx];
    }
    for (int idx = tid; idx < 5 * MM; idx += 256) {       // pad q=75..79
        int m = idx % MM, q = NQ + idx / MM;
        Wsm[m][q] = 0.0f;
    }
    // Stage S[s, d0:d0+64, :] -> Ssm[m][d]  (coalesced reads)
    for (int idx = tid; idx < 64 * MM; idx += 256) {
        int d = idx / MM, m = idx - d * MM;
        Ssm[m][d] = fm[s * (DD * MM) + d0 * MM + idx];
    }
    if (blockIdx.x == 0 && s == 0) {
        for (int i = tid; i < NQ * NS; i += 256) g_l2[i] = 0.0f;
    }
    __syncthreads();

    const int tx = tid & 15;   // d sub-tile
    const int ty = tid >> 4;   // q sub-tile

    float acc[5][4];
#pragma unroll
    for (int j = 0; j < 5; j++)
#pragma unroll
        for (int i = 0; i < 4; i++) acc[j][i] = 0.0f;

#pragma unroll
    for (int m = 0; m < MM; m++) {
        float4 bv = *reinterpret_cast<const float4*>(&Ssm[m][tx * 4]);
#pragma unroll
        for (int j = 0; j < 5; j++) {
            float a = Wsm[m][ty * 5 + j];
            acc[j][0] = fmaf(a, bv.x, acc[j][0]);
            acc[j][1] = fmaf(a, bv.y, acc[j][1]);
            acc[j][2] = fmaf(a, bv.z, acc[j][2]);
            acc[j][3] = fmaf(a, bv.w, acc[j][3]);
        }
    }

#pragma unroll
    for (int j = 0; j < 5; j++) {
        int q = ty * 5 + j;
        if (q < NQ) {
            float4 v = make_float4(acc[j][0], acc[j][1], acc[j][2], acc[j][3]);
            *reinterpret_cast<float4*>(&g_P[(q * NS + s) * DD + d0 + tx * 4]) = v;
        }
    }
}

// ---------------------------------------------------------------------------
// Kernel 2: per-q GEMM + fused L2 accumulation.
// r[s][d] = sum_m W[s,q,m] * Q[q,d,m]; accumulate (r - P)^2 over d into g_l2.
// grid = (5 d-groups of 128, 75 q), block = 224 threads (7 warps),
// thread tile: 4s (per warp) x 4d (per lane).
// ---------------------------------------------------------------------------
__global__ void k2_query_acc(const float* __restrict__ fm,
                             const float* __restrict__ w2) {
    const int q  = blockIdx.y;
    const int d0 = blockIdx.x * 128;

    __shared__ __align__(16) float Wsm[MM][36];   // [m][s], s padded to 32
    __shared__ __align__(16) float Qsm[MM][132];  // [m][d], 128 d (+pad)

    const int tid = threadIdx.x;  // 224

    for (int idx = tid; idx < NS * MM; idx += 224) {
        int s = idx / MM, m = idx - s * MM;
        Wsm[m][s] = w2[(s * NQ + q) * MM + m];
    }
    for (int idx = tid; idx < 7 * MM; idx += 224) {       // pad s=25..31
        int m = idx % MM, s = NS + idx / MM;
        Wsm[m][s] = 0.0f;
    }
    for (int idx = tid; idx < 128 * MM; idx += 224) {
        int d = idx / MM, m = idx - d * MM;
        Qsm[m][d] = fm[(NS + q) * (DD * MM) + d0 * MM + idx];
    }
    __syncthreads();

    const int lane = tid & 31;
    const int warp = tid >> 5;   // 0..6 -> s base = warp*4 (covers 28 rows)

    float acc[4][4];
#pragma unroll
    for (int j = 0; j < 4; j++)
#pragma unroll
        for (int i = 0; i < 4; i++) acc[j][i] = 0.0f;

#pragma unroll
    for (int m = 0; m < MM; m++) {
        float4 bv = *reinterpret_cast<const float4*>(&Qsm[m][lane * 4]);
        float4 av = *reinterpret_cast<const float4*>(&Wsm[m][warp * 4]);
        acc[0][0] = fmaf(av.x, bv.x, acc[0][0]);
        acc[0][1] = fmaf(av.x, bv.y, acc[0][1]);
        acc[0][2] = fmaf(av.x, bv.z, acc[0][2]);
        acc[0][3] = fmaf(av.x, bv.w, acc[0][3]);
        acc[1][0] = fmaf(av.y, bv.x, acc[1][0]);
        acc[1][1] = fmaf(av.y, bv.y, acc[1][1]);
        acc[1][2] = fmaf(av.y, bv.z, acc[1][2]);
        acc[1][3] = fmaf(av.y, bv.w, acc[1][3]);
        acc[2][0] = fmaf(av.z, bv.x, acc[2][0]);
        acc[2][1] = fmaf(av.z, bv.y, acc[2][1]);
        acc[2][2] = fmaf(av.z, bv.z, acc[2][2]);
        acc[2][3] = fmaf(av.z, bv.w, acc[2][3]);
        acc[3][0] = fmaf(av.w, bv.x, acc[3][0]);
        acc[3][1] = fmaf(av.w, bv.y, acc[3][1]);
        acc[3][2] = fmaf(av.w, bv.z, acc[3][2]);
        acc[3][3] = fmaf(av.w, bv.w, acc[3][3]);
    }

    // Fused epilogue: (r - p)^2, reduce over d (4 local + 32 lanes), atomic add.
#pragma unroll
    for (int j = 0; j < 4; j++) {
        int   s    = warp * 4 + j;
        float part = 0.0f;
        if (s < NS) {
            float4 pv = *reinterpret_cast<const float4*>(
                &g_P[(q * NS + s) * DD + d0 + lane * 4]);
            float t0 = acc[j][0] - pv.x;
            float t1 = acc[j][1] - pv.y;
            float t2 = acc[j][2] - pv.z;
            float t3 = acc[j][3] - pv.w;
            part = t0 * t0 + t1 * t1 + t2 * t2 + t3 * t3;
        }
#pragma unroll
        for (int off = 16; off > 0; off >>= 1)
            part += __shfl_down_sync(0xffffffffu, part, off);
        if (lane == 0 && s < NS)
            atomicAdd(&g_l2[q * NS + s], part);
    }
}

// ---------------------------------------------------------------------------
// Kernel 3: scale + log_softmax over s (25 values) per query row.
// logits[q][s] = -raw_l2 * scale / (625 * 500); out = log_softmax(axis=s)
// grid = 75, block = 32 (one warp per row)
// ---------------------------------------------------------------------------
__global__ void k3_softmax(const float* __restrict__ scale,
                           float* __restrict__ out) {
    const int q    = blockIdx.x;
    const int lane = threadIdx.x;

    const float c = -scale[0] / 312500.0f;  // 1/(M^2 * G*Q*Q*SHOT) = 1/(625*500)

    float logit = (lane < NS) ? g_l2[q * NS + lane] * c : -FLT_MAX;

    float mx = logit;
#pragma unroll
    for (int off = 16; off > 0; off >>= 1)
        mx = fmaxf(mx, __shfl_xor_sync(0xffffffffu, mx, off));

    float e = (lane < NS) ? expf(logit - mx) : 0.0f;
    float sum = e;
#pragma unroll
    for (int off = 16; off > 0; off >>= 1)
        sum += __shfl_xor_sync(0xffffffffu, sum, off);

    if (lane < NS)
        out[q * NS + lane] = logit - mx - logf(sum);
}

// ---------------------------------------------------------------------------
extern "C" void kernel_launch(void* const* d_in, const int* in_sizes, int n_in,
                              void* d_out, int out_size) {
    const float* fm    = (const float*)d_in[0];  // (100, 640, 25) f32
    const float* w2    = (const float*)d_in[1];  // (25, 75, 25) f32
    const float* scale = (const float*)d_in[2];  // (1,) f32
    float* out = (float*)d_out;                  // (75, 25) f32

    k1_proj_support<<<dim3(10, 25), 256>>>(fm, w2);
    k2_query_acc<<<dim3(5, NQ), 224>>>(fm, w2);
    k3_softmax<<<NQ, 32>>>(scale, out);
}